// round 16
// baseline (speedup 1.0000x reference)
#include <cuda_runtime.h>
#include <cuda_bf16.h>
#include <cstdint>

#define N_MAX   4096
#define D_MAX   2048
#define NCLS    32
#define MARGIN  0.3f
#define NPART   16
#define GRIDSZ  296
#define MAXSPLT 80               // scratch capacity in tiles

__device__ float           g_sq[N_MAX];      // SOURCE-space row sumsq
__device__ unsigned        g_max2[N_MAX];    // position-space reductions
__device__ unsigned        g_min2[N_MAX];
__device__ int             g_flag;
__device__ int             g_done;
__device__ int             g_perm[N_MAX];    // position -> source row
__device__ int             g_tgtp[N_MAX];    // position -> target (sorted)
__device__ int2            g_tiles[2112];
__device__ int             g_ntiles;
__device__ int             g_ksplit;
__device__ int             g_rdy[MAXSPLT];
__device__ float           g_partial[NPART];
__device__ float           g_scratch[(size_t)MAXSPLT * 3 * 16384];  // 15.7 MB
__device__ __nv_bfloat16   g_xb[(size_t)N_MAX * D_MAX];  // SOURCE-order bf16 rows

// ======= prep: block 0 sorts + builds tile table; other blocks convert ======
__global__ void prep_kernel(const float* __restrict__ x, const int* __restrict__ tgt,
                            int n, int d) {
    if (blockIdx.x == 0) {
        __shared__ int scnt[NCLS], soff[NCLS], sfill[NCLS];
        int tid = threadIdx.x;
        if (tid < NCLS) scnt[tid] = 0;
        if (tid < MAXSPLT) g_rdy[tid] = 0;
        __syncthreads();
        for (int i = tid; i < n; i += blockDim.x) atomicAdd(&scnt[tgt[i]], 1);
        __syncthreads();
        if (tid == 0) {
            int acc = 0;
            for (int c = 0; c < NCLS; c++) { soff[c] = acc; sfill[c] = acc; acc += scnt[c]; }
        }
        __syncthreads();
        for (int i = tid; i < n; i += blockDim.x) {
            int c = tgt[i];
            int pos = atomicAdd(&sfill[c], 1);
            g_perm[pos] = i;
            g_tgtp[pos] = c;
        }
        if (tid == 0) {
            int t0 = tgt[0];
            int c0 = scnt[0];
            g_flag = (t0 == 0) ? ((n - c0) > 0 ? 1 : 0) : (c0 > 0 ? 1 : 0);
            g_done = 0;
            // tile table: 128x128 tiles. per-class triangular + class0 strip
            int nt = 0;
            int nb = (n + 127) >> 7;
            for (int c = 0; c < NCLS; c++) {
                int off = scnt[c] ? soff[c] : 0;
                int t128 = (scnt[c] + 127) >> 7;
                for (int a = 0; a < t128; a++)
                    for (int b = a; b < t128; b++)
                        g_tiles[nt++] = make_int2(off + a * 128, off + b * 128);
            }
            int ti0 = (c0 + 127) >> 7;
            for (int a = 0; a < ti0; a++)
                for (int jb = (c0 >> 7); jb < nb; jb++)
                    g_tiles[nt++] = make_int2(a * 128, jb * 128);
            g_ntiles = nt;
            // split factor: all work units must be resident simultaneously
            int nkt = d >> 6;                      // d / 64
            int ks = 1;
            if (nt <= MAXSPLT) {
                if (nt * 4 <= GRIDSZ && (nkt & 3) == 0 && nkt >= 8) ks = 4;
                else if (nt * 2 <= GRIDSZ && (nkt & 1) == 0 && nkt >= 4) ks = 2;
            }
            g_ksplit = ks;
        }
        return;
    }

    // ---- convert blocks: source-order norms + bf16 (8 rows per block) ----
    int row = (blockIdx.x - 1) * 8 + (threadIdx.x >> 5);
    int lane = threadIdx.x & 31;
    if (row >= n) return;
    const float4* src = (const float4*)(x + (size_t)row * d);
    uint4* orow = (uint4*)(g_xb + (size_t)row * d);
    int nv = d >> 3;
    float s = 0.f;
    for (int v = lane; v < nv; v += 32) {
        float4 f0 = src[v * 2];
        float4 f1 = src[v * 2 + 1];
        s += f0.x * f0.x + f0.y * f0.y + f0.z * f0.z + f0.w * f0.w;
        s += f1.x * f1.x + f1.y * f1.y + f1.z * f1.z + f1.w * f1.w;
        __nv_bfloat162 h0 = __floats2bfloat162_rn(f0.x, f0.y);
        __nv_bfloat162 h1 = __floats2bfloat162_rn(f0.z, f0.w);
        __nv_bfloat162 h2 = __floats2bfloat162_rn(f1.x, f1.y);
        __nv_bfloat162 h3 = __floats2bfloat162_rn(f1.z, f1.w);
        uint4 o;
        o.x = *(uint32_t*)&h0; o.y = *(uint32_t*)&h1;
        o.z = *(uint32_t*)&h2; o.w = *(uint32_t*)&h3;
        orow[v] = o;
    }
    #pragma unroll
    for (int o = 16; o; o >>= 1) s += __shfl_xor_sync(0xffffffffu, s, o);
    if (lane == 0) {
        g_sq[row]   = s;
        g_max2[row] = 0u;
        g_min2[row] = 0x7f800000u;
    }
}

// ======================= PTX helpers (baseline ISA only) ====================
__device__ __forceinline__ uint32_t smem_u32(const void* p) {
    uint32_t a;
    asm("{ .reg .u64 t; cvta.to.shared.u64 t, %1; cvt.u32.u64 %0, t; }" : "=r"(a) : "l"(p));
    return a;
}
#define CP16(sa, ga) \
    asm volatile("cp.async.cg.shared.global [%0], [%1], 16;" :: "r"(sa), "l"(ga) : "memory")
#define CP_COMMIT()  asm volatile("cp.async.commit_group;" ::: "memory")
#define CP_WAIT1()   asm volatile("cp.async.wait_group 1;" ::: "memory")
#define CP_WAIT0()   asm volatile("cp.async.wait_group 0;" ::: "memory")

#define LDSM_X4(r, a) \
    asm volatile("ldmatrix.sync.aligned.m8n8.x4.shared.b16 {%0,%1,%2,%3}, [%4];" \
        : "=r"((r)[0]), "=r"((r)[1]), "=r"((r)[2]), "=r"((r)[3]) : "r"(a))
#define LDSM_X2(r, a) \
    asm volatile("ldmatrix.sync.aligned.m8n8.x2.shared.b16 {%0,%1}, [%2];" \
        : "=r"((r)[0]), "=r"((r)[1]) : "r"(a))

#define MMA16816(c, a, b) \
    asm volatile("mma.sync.aligned.m16n8k16.row.col.f32.bf16.bf16.f32 " \
        "{%0,%1,%2,%3},{%4,%5,%6,%7},{%8,%9},{%0,%1,%2,%3};" \
        : "+f"((c)[0]), "+f"((c)[1]), "+f"((c)[2]), "+f"((c)[3]) \
        : "r"((a)[0]), "r"((a)[1]), "r"((a)[2]), "r"((a)[3]), "r"((b)[0]), "r"((b)[1]))

// ====== sparse-tile bf16 GEMM (128x128, split-K) + reductions + loss ========
#define BM    128
#define BKE   64                 // bf16 elems per K stage (128 B rows)
#define SROW  144
#define STG_M (BM * SROW)        // 18432
#define STG   (2 * STG_M)        // 36864
#define NSTG  3
#define SM_RED   (NSTG * STG)              // 110592
#define SM_TOTAL (SM_RED + 2048)           // 112640

__global__ void __launch_bounds__(256, 2)
gemm_mma_kernel(float* __restrict__ out, int n, int d) {
    extern __shared__ char smem[];
    const uint32_t smemu = smem_u32(smem);
    const int tid  = threadIdx.x;
    const int wid  = tid >> 5;
    const int lane = tid & 31;
    const size_t dB = (size_t)d * 2;

    const int mWarp = (wid >> 2) * 64;
    const int nWarp = (wid & 3) * 32;
    const uint32_t aRowOff = (mWarp + (lane & 15)) * SROW + ((lane >> 4) & 1) * 16;
    const uint32_t bRowOff = (nWarp + (lane & 7))  * SROW + ((lane >> 3) & 1) * 16;
    const unsigned UINF = 0x7f800000u;

    const int ntiles = g_ntiles;
    const int ks     = g_ksplit;
    const int nkt    = d / BKE;
    const int qn     = nkt / ks;
    const int nwork  = ntiles * ks;

    for (int w = blockIdx.x; w < nwork; w += gridDim.x) {
        int tix = w / ks;
        int kq  = w - tix * ks;
        int2 tile = g_tiles[tix];
        const int iBase = tile.x;
        const int jBase = tile.y;
        const int ktBeg = kq * qn;

        // cache gather pointers (128 rows x 8 chunks per matrix, 4/thread)
        const char* srcA[4];
        const char* srcB[4];
        #pragma unroll
        for (int t = 0; t < 4; t++) {
            int r = (tid + t * 256) >> 3;
            srcA[t] = (const char*)g_xb + (size_t)g_perm[min(iBase + r, n - 1)] * dB;
            srcB[t] = (const char*)g_xb + (size_t)g_perm[min(jBase + r, n - 1)] * dB;
        }

        float acc[4][4][4];
        #pragma unroll
        for (int mt = 0; mt < 4; mt++)
            #pragma unroll
            for (int nt = 0; nt < 4; nt++)
                #pragma unroll
                for (int e = 0; e < 4; e++) acc[mt][nt][e] = 0.f;

        auto issue = [&](int s, int kt) {
            uint32_t aS = smemu + s * STG;
            uint32_t bS = aS + STG_M;
            int koff = kt * 128;
            #pragma unroll
            for (int t = 0; t < 4; t++) {
                int chunk = tid + t * 256;
                uint32_t so = (chunk >> 3) * SROW + (chunk & 7) * 16;
                CP16(aS + so, srcA[t] + koff + (chunk & 7) * 16);
                CP16(bS + so, srcB[t] + koff + (chunk & 7) * 16);
            }
        };

        issue(0, ktBeg); CP_COMMIT();
        issue(1, ktBeg + 1); CP_COMMIT();

        for (int lk = 0; lk < qn; lk++) {
            CP_WAIT1();
            __syncthreads();
            if (lk + 2 < qn) { issue((lk + 2) % NSTG, ktBeg + lk + 2); }
            CP_COMMIT();

            int s = lk % NSTG;
            uint32_t aS = smemu + s * STG;
            uint32_t bS = aS + STG_M;
            #pragma unroll
            for (int kk = 0; kk < 4; kk++) {
                uint32_t rb[4][2];
                #pragma unroll
                for (int nt = 0; nt < 4; nt++)
                    LDSM_X2(rb[nt], bS + bRowOff + nt * 8 * SROW + kk * 32);
                #pragma unroll
                for (int mt = 0; mt < 4; mt++) {
                    uint32_t ra[4];
                    LDSM_X4(ra, aS + aRowOff + mt * 16 * SROW + kk * 32);
                    #pragma unroll
                    for (int nt = 0; nt < 4; nt++)
                        MMA16816(acc[mt][nt], ra, rb[nt]);
                }
            }
        }
        CP_WAIT0();
        __syncthreads();

        // --- split-K writer: dump partial, signal, next work unit ------------
        if (kq < ks - 1) {
            float* dst = g_scratch + ((size_t)tix * 3 + kq) * 16384;
            #pragma unroll
            for (int mt = 0; mt < 4; mt++)
                #pragma unroll
                for (int nt = 0; nt < 4; nt++)
                    #pragma unroll
                    for (int e = 0; e < 4; e++)
                        dst[(mt * 16 + nt * 4 + e) * 256 + tid] = acc[mt][nt][e];
            __syncthreads();
            __threadfence();
            if (tid == 0) atomicAdd(&g_rdy[tix], 1);
            continue;
        }

        // --- split-K merger: wait for writers, add partials (fixed order) ----
        if (ks > 1) {
            if (tid == 0) {
                while (*(volatile int*)&g_rdy[tix] < ks - 1) __nanosleep(64);
            }
            __syncthreads();
            __threadfence();
            const float* base = g_scratch + (size_t)tix * 3 * 16384;
            for (int slot = 0; slot < ks - 1; slot++) {
                const float* src = base + (size_t)slot * 16384;
                #pragma unroll
                for (int mt = 0; mt < 4; mt++)
                    #pragma unroll
                    for (int nt = 0; nt < 4; nt++)
                        #pragma unroll
                        for (int e = 0; e < 4; e++)
                            acc[mt][nt][e] += src[(mt * 16 + nt * 4 + e) * 256 + tid];
            }
        }

        // --- epilogue (position space; data via perm) ------------------------
        float sqi[8], sqj[8];
        int   ti[8], tj[8];
        #pragma unroll
        for (int mt = 0; mt < 4; mt++)
            #pragma unroll
            for (int h = 0; h < 2; h++) {
                int pos = min(iBase + mWarp + mt * 16 + (lane >> 2) + h * 8, n - 1);
                sqi[mt * 2 + h] = g_sq[g_perm[pos]];
                ti[mt * 2 + h]  = g_tgtp[pos];
            }
        #pragma unroll
        for (int nt = 0; nt < 4; nt++)
            #pragma unroll
            for (int pp = 0; pp < 2; pp++) {
                int pos = min(jBase + nWarp + nt * 8 + 2 * (lane & 3) + pp, n - 1);
                sqj[nt * 2 + pp] = g_sq[g_perm[pos]];
                tj[nt * 2 + pp]  = g_tgtp[pos];
            }

        unsigned rmax[8], rmin[8], cmax[8], cmin[8];
        #pragma unroll
        for (int q = 0; q < 8; q++) { rmax[q] = 0u; rmin[q] = UINF; cmax[q] = 0u; cmin[q] = UINF; }

        #pragma unroll
        for (int mt = 0; mt < 4; mt++)
            #pragma unroll
            for (int nt = 0; nt < 4; nt++)
                #pragma unroll
                for (int e = 0; e < 4; e++) {
                    int h = e >> 1, pp = e & 1;
                    int ri = mt * 2 + h, cj = nt * 2 + pp;
                    float d2 = fmaxf(sqi[ri] + sqj[cj] - 2.f * acc[mt][nt][(h << 1) | pp], 1e-12f);
                    unsigned b = __float_as_uint(d2);
                    bool same = (ti[ri] == tj[cj]);
                    bool zn   = !same && (ti[ri] == 0 || tj[cj] == 0);
                    if (same) { rmax[ri] = max(rmax[ri], b); cmax[cj] = max(cmax[cj], b); }
                    if (zn)   { rmin[ri] = min(rmin[ri], b); cmin[cj] = min(cmin[cj], b); }
                }

        unsigned* sredmax = (unsigned*)(smem + SM_RED);
        unsigned* sredmin = sredmax + 256;
        sredmax[tid] = 0u;
        sredmin[tid] = UINF;
        __syncthreads();

        #pragma unroll
        for (int mt = 0; mt < 4; mt++)
            #pragma unroll
            for (int h = 0; h < 2; h++) {
                int q = mt * 2 + h;
                int loc = mWarp + mt * 16 + (lane >> 2) + h * 8;
                if (rmax[q]) atomicMax(&sredmax[loc], rmax[q]);
                if (rmin[q] != UINF) atomicMin(&sredmin[loc], rmin[q]);
            }
        #pragma unroll
        for (int nt = 0; nt < 4; nt++)
            #pragma unroll
            for (int pp = 0; pp < 2; pp++) {
                int q = nt * 2 + pp;
                int loc = 128 + nWarp + nt * 8 + 2 * (lane & 3) + pp;
                if (cmax[q]) atomicMax(&sredmax[loc], cmax[q]);
                if (cmin[q] != UINF) atomicMin(&sredmin[loc], cmin[q]);
            }
        __syncthreads();

        {
            int pos = (tid < 128) ? min(iBase + tid, n - 1) : min(jBase + (tid - 128), n - 1);
            if (sredmax[tid]) atomicMax(&g_max2[pos], sredmax[tid]);
            if (sredmin[tid] != UINF) atomicMin(&g_min2[pos], sredmin[tid]);
        }
        __syncthreads();
    }

    // --- last-CTA tail: full loss reduction ----------------------------------
    __threadfence();
    __shared__ int amlast;
    if (tid == 0) amlast = (atomicAdd(&g_done, 1) == (int)gridDim.x - 1);
    __syncthreads();
    if (amlast) {
        int flag = g_flag;
        float s = 0.f;
        for (int i = tid; i < n; i += 256) {
            float ap = sqrtf(__uint_as_float(__ldcg(&g_max2[i])));
            float an = flag ? sqrtf(__uint_as_float(__ldcg(&g_min2[i]))) : 0.f;
            s += fmaxf(ap - an + MARGIN, 0.f);
        }
        float* ssum = (float*)(smem + SM_RED);
        ssum[tid] = s;
        __syncthreads();
        #pragma unroll
        for (int o = 128; o; o >>= 1) {
            if (tid < o) ssum[tid] += ssum[tid + o];
            __syncthreads();
        }
        if (tid == 0) out[0] = ssum[0] / (float)n;
    }
}

// ======================= legacy fp32 fallback (proven, R2) ==================
__global__ void legacy_prep(const float* __restrict__ x, const int* __restrict__ tgt,
                            int n, int d) {
    int warp = (blockIdx.x * blockDim.x + threadIdx.x) >> 5;
    int lane = threadIdx.x & 31;
    if (warp < n) {
        const float4* row = (const float4*)(x + (size_t)warp * d);
        int nv = d >> 2;
        float s = 0.f;
        for (int v = lane; v < nv; v += 32) {
            float4 f = row[v];
            s += f.x * f.x + f.y * f.y + f.z * f.z + f.w * f.w;
        }
        #pragma unroll
        for (int o = 16; o; o >>= 1) s += __shfl_xor_sync(0xffffffffu, s, o);
        if (lane == 0) {
            g_sq[warp]   = s;
            g_max2[warp] = 0u;
            g_min2[warp] = 0x7f800000u;
        }
    }
    if (blockIdx.x == 0) {
        int t0 = tgt[0];
        int loc = 0;
        for (int j = threadIdx.x; j < n; j += blockDim.x) {
            int tj = tgt[j];
            if ((t0 != tj) && (t0 == 0 || tj == 0)) loc = 1;
        }
        int f = __syncthreads_or(loc);
        if (threadIdx.x == 0) g_flag = f;
    }
}

#define LT    128
#define LKT   16
#define LPAD  4
__global__ void __launch_bounds__(256, 2)
gemm_reduce_legacy(const float* __restrict__ x, const int* __restrict__ tgt,
                   int n, int d, int nb) {
    int p = blockIdx.x, bi = 0, rem = p;
    while (rem >= nb - bi) { rem -= (nb - bi); bi++; }
    int bj = bi + rem;
    const int iBase = bi * LT;
    const int jBase = bj * LT;
    const int tid = threadIdx.x;
    const int tx = tid & 15;
    const int ty = tid >> 4;

    __shared__ float As[LKT][LT + LPAD];
    __shared__ float Bs[LKT][LT + LPAD];
    __shared__ unsigned sredmax[2 * LT];
    __shared__ unsigned sredmin[2 * LT];

    float acc[8][8];
    #pragma unroll
    for (int r = 0; r < 8; r++)
        #pragma unroll
        for (int c = 0; c < 8; c++) acc[r][c] = 0.f;

    const int nkt = d / LKT;
    float4 pa[2], pb[2];
    #pragma unroll
    for (int u = 0; u < 2; u++) {
        int idx = tid + u * 256, r = idx >> 2, c4 = idx & 3;
        pa[u] = *(const float4*)(x + (size_t)(iBase + r) * d + c4 * 4);
        pb[u] = *(const float4*)(x + (size_t)(jBase + r) * d + c4 * 4);
    }
    #pragma unroll
    for (int u = 0; u < 2; u++) {
        int idx = tid + u * 256, r = idx >> 2, c4 = idx & 3;
        As[c4*4+0][r]=pa[u].x; As[c4*4+1][r]=pa[u].y; As[c4*4+2][r]=pa[u].z; As[c4*4+3][r]=pa[u].w;
        Bs[c4*4+0][r]=pb[u].x; Bs[c4*4+1][r]=pb[u].y; Bs[c4*4+2][r]=pb[u].z; Bs[c4*4+3][r]=pb[u].w;
    }
    __syncthreads();
    for (int kt = 0; kt < nkt; kt++) {
        if (kt + 1 < nkt) {
            int k0 = (kt + 1) * LKT;
            #pragma unroll
            for (int u = 0; u < 2; u++) {
                int idx = tid + u * 256, r = idx >> 2, c4 = idx & 3;
                pa[u] = *(const float4*)(x + (size_t)(iBase + r) * d + k0 + c4 * 4);
                pb[u] = *(const float4*)(x + (size_t)(jBase + r) * d + k0 + c4 * 4);
            }
        }
        #pragma unroll
        for (int k = 0; k < LKT; k++) {
            float a[8], b[8];
            *(float4*)(a)   = *(const float4*)&As[k][ty*8];
            *(float4*)(a+4) = *(const float4*)&As[k][ty*8+4];
            *(float4*)(b)   = *(const float4*)&Bs[k][tx*8];
            *(float4*)(b+4) = *(const float4*)&Bs[k][tx*8+4];
            #pragma unroll
            for (int r = 0; r < 8; r++)
                #pragma unroll
                for (int c = 0; c < 8; c++) acc[r][c] += a[r] * b[c];
        }
        __syncthreads();
        if (kt + 1 < nkt) {
            #pragma unroll
            for (int u = 0; u < 2; u++) {
                int idx = tid + u * 256, r = idx >> 2, c4 = idx & 3;
                As[c4*4+0][r]=pa[u].x; As[c4*4+1][r]=pa[u].y; As[c4*4+2][r]=pa[u].z; As[c4*4+3][r]=pa[u].w;
                Bs[c4*4+0][r]=pb[u].x; Bs[c4*4+1][r]=pb[u].y; Bs[c4*4+2][r]=pb[u].z; Bs[c4*4+3][r]=pb[u].w;
            }
            __syncthreads();
        }
    }

    float sqi[8], sqj[8];
    int ti8[8], tj8[8];
    #pragma unroll
    for (int r = 0; r < 8; r++) { int i = iBase + ty*8 + r; sqi[r] = g_sq[i]; ti8[r] = tgt[i]; }
    #pragma unroll
    for (int c = 0; c < 8; c++) { int j = jBase + tx*8 + c; sqj[c] = g_sq[j]; tj8[c] = tgt[j]; }

    const float INF = __uint_as_float(0x7f800000u);
    float rmax[8], rmin[8], cmax[8], cmin[8];
    #pragma unroll
    for (int r = 0; r < 8; r++) { rmax[r] = 0.f; rmin[r] = INF; }
    #pragma unroll
    for (int c = 0; c < 8; c++) { cmax[c] = 0.f; cmin[c] = INF; }
    #pragma unroll
    for (int r = 0; r < 8; r++)
        #pragma unroll
        for (int c = 0; c < 8; c++) {
            float d2 = fmaxf(sqi[r] + sqj[c] - 2.f * acc[r][c], 1e-12f);
            bool same = (ti8[r] == tj8[c]);
            bool zn = !same && (ti8[r] == 0 || tj8[c] == 0);
            if (same) { rmax[r] = fmaxf(rmax[r], d2); cmax[c] = fmaxf(cmax[c], d2); }
            if (zn)   { rmin[r] = fminf(rmin[r], d2); cmin[c] = fminf(cmin[c], d2); }
        }
    sredmax[tid] = 0u; sredmin[tid] = 0x7f800000u;
    __syncthreads();
    #pragma unroll
    for (int r = 0; r < 8; r++) {
        atomicMax(&sredmax[ty*8+r], __float_as_uint(rmax[r]));
        atomicMin(&sredmin[ty*8+r], __float_as_uint(rmin[r]));
    }
    #pragma unroll
    for (int c = 0; c < 8; c++) {
        atomicMax(&sredmax[LT + tx*8+c], __float_as_uint(cmax[c]));
        atomicMin(&sredmin[LT + tx*8+c], __float_as_uint(cmin[c]));
    }
    __syncthreads();
    int row = (tid < LT) ? (iBase + tid) : (jBase + (tid - LT));
    atomicMax(&g_max2[row], sredmax[tid]);
    atomicMin(&g_min2[row], sredmin[tid]);
}

__global__ void partial_kernel(int n) {
    __shared__ float ssum[256];
    int flag = g_flag;
    int chunk = (n + NPART - 1) / NPART;
    int beg = blockIdx.x * chunk;
    int end = min(beg + chunk, n);
    float s = 0.f;
    for (int i = beg + (int)threadIdx.x; i < end; i += blockDim.x) {
        float ap = sqrtf(__uint_as_float(g_max2[i]));
        float an = flag ? sqrtf(__uint_as_float(g_min2[i])) : 0.f;
        s += fmaxf(ap - an + MARGIN, 0.f);
    }
    ssum[threadIdx.x] = s;
    __syncthreads();
    #pragma unroll
    for (int o = 128; o; o >>= 1) {
        if (threadIdx.x < o) ssum[threadIdx.x] += ssum[threadIdx.x + o];
        __syncthreads();
    }
    if (threadIdx.x == 0) g_partial[blockIdx.x] = ssum[0];
}

__global__ void final_kernel(float* __restrict__ out, int n) {
    if (threadIdx.x == 0) {
        float s = 0.f;
        #pragma unroll
        for (int b = 0; b < NPART; b++) s += g_partial[b];
        out[0] = s / (float)n;
    }
}

// ======================= host launcher ======================================
extern "C" void kernel_launch(void* const* d_in, const int* in_sizes, int n_in,
                              void* d_out, int out_size) {
    const float* x   = (const float*)d_in[0];
    const int*   tgt = (const int*)d_in[1];   // int32 (JAX x64 disabled)
    int n = in_sizes[1];
    int d = in_sizes[0] / n;

    bool tc_ok = (n % 128 == 0) && (d % BKE == 0) && (d / BKE >= 2) &&
                 (n <= N_MAX) && ((size_t)n * d <= (size_t)N_MAX * D_MAX);
    if (tc_ok) {
        static bool attr_set = false;
        if (!attr_set) {
            cudaFuncSetAttribute(gemm_mma_kernel,
                                 cudaFuncAttributeMaxDynamicSharedMemorySize, SM_TOTAL);
            attr_set = true;
        }
        prep_kernel<<<1 + n / 8, 256>>>(x, tgt, n, d);
        gemm_mma_kernel<<<GRIDSZ, 256, SM_TOTAL>>>((float*)d_out, n, d);
    } else {
        legacy_prep<<<(n + 7) / 8, 256>>>(x, tgt, n, d);
        int nb = n / LT;
        int nblocks = nb * (nb + 1) / 2;
        gemm_reduce_legacy<<<nblocks, 256>>>(x, tgt, n, d, nb);
        partial_kernel<<<NPART, 256>>>(n);
        final_kernel<<<1, 32>>>((float*)d_out, n);
    }
}

// round 17
// speedup vs baseline: 1.1348x; 1.1348x over previous
#include <cuda_runtime.h>
#include <cuda_bf16.h>
#include <cstdint>

#define N_MAX   4096
#define D_MAX   2048
#define NCLS    32
#define MARGIN  0.3f
#define NPART   16
#define GRIDSZ  296
#define MAXSPLT 160              // scratch capacity in tiles

__device__ float           g_sq[N_MAX];      // SOURCE-space row sumsq
__device__ unsigned        g_max2[N_MAX];    // position-space reductions
__device__ unsigned        g_min2[N_MAX];
__device__ int             g_flag;
__device__ int             g_done;
__device__ int             g_perm[N_MAX];    // position -> source row
__device__ int             g_tgtp[N_MAX];    // position -> target (sorted)
__device__ int2            g_tiles[2112];
__device__ int             g_ntiles;
__device__ int             g_ksplit;
__device__ int             g_rdy[MAXSPLT];
__device__ float           g_partial[NPART];
__device__ float           g_scratch[(size_t)MAXSPLT * 3 * 16384];  // 31.5 MB
__device__ __nv_bfloat16   g_xb[(size_t)N_MAX * D_MAX];  // SOURCE-order bf16 rows

// ======= prep: block 0 sorts + builds tile table; other blocks convert ======
__global__ void prep_kernel(const float* __restrict__ x, const int* __restrict__ tgt,
                            int n, int d) {
    if (blockIdx.x == 0) {
        __shared__ int scnt[NCLS], soff[NCLS], sfill[NCLS];
        int tid = threadIdx.x;
        if (tid < NCLS) scnt[tid] = 0;
        if (tid < MAXSPLT) g_rdy[tid] = 0;
        __syncthreads();
        for (int i = tid; i < n; i += blockDim.x) atomicAdd(&scnt[tgt[i]], 1);
        __syncthreads();
        if (tid == 0) {
            int acc = 0;
            for (int c = 0; c < NCLS; c++) { soff[c] = acc; sfill[c] = acc; acc += scnt[c]; }
        }
        __syncthreads();
        for (int i = tid; i < n; i += blockDim.x) {
            int c = tgt[i];
            int pos = atomicAdd(&sfill[c], 1);
            g_perm[pos] = i;
            g_tgtp[pos] = c;
        }
        if (tid == 0) {
            int t0 = tgt[0];
            int c0 = scnt[0];
            g_flag = (t0 == 0) ? ((n - c0) > 0 ? 1 : 0) : (c0 > 0 ? 1 : 0);
            g_done = 0;
            // tile table: 128x128. per-class triangular + class0 strip
            int nt = 0;
            int nb = (n + 127) >> 7;
            for (int c = 0; c < NCLS; c++) {
                int off = soff[c];
                int t128 = (scnt[c] + 127) >> 7;
                for (int a = 0; a < t128; a++)
                    for (int b = a; b < t128; b++)
                        g_tiles[nt++] = make_int2(off + a * 128, off + b * 128);
            }
            int ti0 = (c0 + 127) >> 7;
            for (int a = 0; a < ti0; a++)
                for (int jb = (c0 >> 7); jb < nb; jb++)
                    g_tiles[nt++] = make_int2(a * 128, jb * 128);
            g_ntiles = nt;
            // largest split with ALL work units simultaneously resident
            int nkt = d >> 6;                      // d / 64
            int ks = 1;
            if (nt <= MAXSPLT) {
                if      (nt * 4 <= GRIDSZ && nkt >= 8) ks = 4;
                else if (nt * 3 <= GRIDSZ && nkt >= 6) ks = 3;
                else if (nt * 2 <= GRIDSZ && nkt >= 4) ks = 2;
            }
            g_ksplit = ks;
        }
        return;
    }

    // ---- convert blocks: source-order norms + bf16 (8 rows per block) ----
    int row = (blockIdx.x - 1) * 8 + (threadIdx.x >> 5);
    int lane = threadIdx.x & 31;
    if (row >= n) return;
    const float4* src = (const float4*)(x + (size_t)row * d);
    uint4* orow = (uint4*)(g_xb + (size_t)row * d);
    int nv = d >> 3;
    float s = 0.f;
    for (int v = lane; v < nv; v += 32) {
        float4 f0 = src[v * 2];
        float4 f1 = src[v * 2 + 1];
        s += f0.x * f0.x + f0.y * f0.y + f0.z * f0.z + f0.w * f0.w;
        s += f1.x * f1.x + f1.y * f1.y + f1.z * f1.z + f1.w * f1.w;
        __nv_bfloat162 h0 = __floats2bfloat162_rn(f0.x, f0.y);
        __nv_bfloat162 h1 = __floats2bfloat162_rn(f0.z, f0.w);
        __nv_bfloat162 h2 = __floats2bfloat162_rn(f1.x, f1.y);
        __nv_bfloat162 h3 = __floats2bfloat162_rn(f1.z, f1.w);
        uint4 o;
        o.x = *(uint32_t*)&h0; o.y = *(uint32_t*)&h1;
        o.z = *(uint32_t*)&h2; o.w = *(uint32_t*)&h3;
        orow[v] = o;
    }
    #pragma unroll
    for (int o = 16; o; o >>= 1) s += __shfl_xor_sync(0xffffffffu, s, o);
    if (lane == 0) {
        g_sq[row]   = s;
        g_max2[row] = 0u;
        g_min2[row] = 0x7f800000u;
    }
}

// ======================= PTX helpers (baseline ISA only) ====================
__device__ __forceinline__ uint32_t smem_u32(const void* p) {
    uint32_t a;
    asm("{ .reg .u64 t; cvta.to.shared.u64 t, %1; cvt.u32.u64 %0, t; }" : "=r"(a) : "l"(p));
    return a;
}
#define CP16(sa, ga) \
    asm volatile("cp.async.cg.shared.global [%0], [%1], 16;" :: "r"(sa), "l"(ga) : "memory")
#define CP_COMMIT()  asm volatile("cp.async.commit_group;" ::: "memory")
#define CP_WAIT1()   asm volatile("cp.async.wait_group 1;" ::: "memory")
#define CP_WAIT0()   asm volatile("cp.async.wait_group 0;" ::: "memory")

#define LDSM_X4(r, a) \
    asm volatile("ldmatrix.sync.aligned.m8n8.x4.shared.b16 {%0,%1,%2,%3}, [%4];" \
        : "=r"((r)[0]), "=r"((r)[1]), "=r"((r)[2]), "=r"((r)[3]) : "r"(a))
#define LDSM_X2(r, a) \
    asm volatile("ldmatrix.sync.aligned.m8n8.x2.shared.b16 {%0,%1}, [%2];" \
        : "=r"((r)[0]), "=r"((r)[1]) : "r"(a))

#define MMA16816(c, a, b) \
    asm volatile("mma.sync.aligned.m16n8k16.row.col.f32.bf16.bf16.f32 " \
        "{%0,%1,%2,%3},{%4,%5,%6,%7},{%8,%9},{%0,%1,%2,%3};" \
        : "+f"((c)[0]), "+f"((c)[1]), "+f"((c)[2]), "+f"((c)[3]) \
        : "r"((a)[0]), "r"((a)[1]), "r"((a)[2]), "r"((a)[3]), "r"((b)[0]), "r"((b)[1]))

// ====== sparse-tile bf16 GEMM (128x128, split-K) + reductions + loss ========
#define BM    128
#define BKE   64                 // bf16 elems per K stage (128 B rows)
#define SROW  144
#define STG_M (BM * SROW)        // 18432
#define STG   (2 * STG_M)        // 36864
#define NSTG  3
#define SM_RED   (NSTG * STG)              // 110592
#define SM_TOTAL (SM_RED + 2048)           // 112640

__global__ void __launch_bounds__(256, 2)
gemm_mma_kernel(float* __restrict__ out, int n, int d) {
    extern __shared__ char smem[];
    const uint32_t smemu = smem_u32(smem);
    const int tid  = threadIdx.x;
    const int wid  = tid >> 5;
    const int lane = tid & 31;
    const size_t dB = (size_t)d * 2;
    const char* xb = (const char*)g_xb;

    const int mWarp = (wid >> 2) * 64;
    const int nWarp = (wid & 3) * 32;
    const uint32_t aRowOff = (mWarp + (lane & 15)) * SROW + ((lane >> 4) & 1) * 16;
    const uint32_t bRowOff = (nWarp + (lane & 7))  * SROW + ((lane >> 3) & 1) * 16;
    const unsigned UINF = 0x7f800000u;

    const int ntiles = g_ntiles;
    const int ks     = g_ksplit;
    const int nkt    = d / BKE;
    const int nwork  = ntiles * ks;

    for (int w = blockIdx.x; w < nwork; w += gridDim.x) {
        int tix = w / ks;
        int kq  = w - tix * ks;
        int2 tile = g_tiles[tix];
        const int iBase = tile.x;
        const int jBase = tile.y;
        const int ktBeg = kq * nkt / ks;
        const int qn    = (kq + 1) * nkt / ks - ktBeg;

        // cache gathered ROW INDICES (ints, not pointers -> lower reg pressure)
        int rowsA[4], rowsB[4];
        #pragma unroll
        for (int t = 0; t < 4; t++) {
            int r = (tid + t * 256) >> 3;
            rowsA[t] = g_perm[min(iBase + r, n - 1)];
            rowsB[t] = g_perm[min(jBase + r, n - 1)];
        }

        float acc[4][4][4];
        #pragma unroll
        for (int mt = 0; mt < 4; mt++)
            #pragma unroll
            for (int nt = 0; nt < 4; nt++)
                #pragma unroll
                for (int e = 0; e < 4; e++) acc[mt][nt][e] = 0.f;

        auto issue = [&](int s, int kt) {
            uint32_t aS = smemu + s * STG;
            uint32_t bS = aS + STG_M;
            int koff = kt * 128;
            #pragma unroll
            for (int t = 0; t < 4; t++) {
                int chunk = tid + t * 256;
                uint32_t so = (chunk >> 3) * SROW + (chunk & 7) * 16;
                int co = koff + (chunk & 7) * 16;
                CP16(aS + so, xb + (size_t)rowsA[t] * dB + co);
                CP16(bS + so, xb + (size_t)rowsB[t] * dB + co);
            }
        };

        issue(0, ktBeg); CP_COMMIT();
        issue(1, ktBeg + 1); CP_COMMIT();

        for (int lk = 0; lk < qn; lk++) {
            CP_WAIT1();
            __syncthreads();
            if (lk + 2 < qn) { issue((lk + 2) % NSTG, ktBeg + lk + 2); }
            CP_COMMIT();

            int s = lk % NSTG;
            uint32_t aS = smemu + s * STG;
            uint32_t bS = aS + STG_M;
            #pragma unroll
            for (int kk = 0; kk < 4; kk++) {
                uint32_t rb[4][2];
                #pragma unroll
                for (int nt = 0; nt < 4; nt++)
                    LDSM_X2(rb[nt], bS + bRowOff + nt * 8 * SROW + kk * 32);
                #pragma unroll
                for (int mt = 0; mt < 4; mt++) {
                    uint32_t ra[4];
                    LDSM_X4(ra, aS + aRowOff + mt * 16 * SROW + kk * 32);
                    #pragma unroll
                    for (int nt = 0; nt < 4; nt++)
                        MMA16816(acc[mt][nt], ra, rb[nt]);
                }
            }
        }
        CP_WAIT0();
        __syncthreads();

        // --- split-K writer: dump partial, signal, done with this unit -------
        if (kq < ks - 1) {
            float* dst = g_scratch + ((size_t)tix * 3 + kq) * 16384;
            #pragma unroll
            for (int mt = 0; mt < 4; mt++)
                #pragma unroll
                for (int nt = 0; nt < 4; nt++)
                    #pragma unroll
                    for (int e = 0; e < 4; e++)
                        dst[(mt * 16 + nt * 4 + e) * 256 + tid] = acc[mt][nt][e];
            __syncthreads();
            __threadfence();
            if (tid == 0) atomicAdd(&g_rdy[tix], 1);
            continue;
        }

        // --- split-K merger: wait for writers, add partials (fixed order) ----
        if (ks > 1) {
            if (tid == 0) {
                while (*(volatile int*)&g_rdy[tix] < ks - 1) __nanosleep(64);
            }
            __syncthreads();
            __threadfence();
            const float* base = g_scratch + (size_t)tix * 3 * 16384;
            for (int slot = 0; slot < ks - 1; slot++) {
                const float* srcp = base + (size_t)slot * 16384;
                #pragma unroll
                for (int mt = 0; mt < 4; mt++)
                    #pragma unroll
                    for (int nt = 0; nt < 4; nt++)
                        #pragma unroll
                        for (int e = 0; e < 4; e++)
                            acc[mt][nt][e] += srcp[(mt * 16 + nt * 4 + e) * 256 + tid];
            }
        }

        // --- epilogue (position space; data via perm) ------------------------
        float sqi[8], sqj[8];
        int   ti[8], tj[8];
        #pragma unroll
        for (int mt = 0; mt < 4; mt++)
            #pragma unroll
            for (int h = 0; h < 2; h++) {
                int pos = min(iBase + mWarp + mt * 16 + (lane >> 2) + h * 8, n - 1);
                sqi[mt * 2 + h] = g_sq[g_perm[pos]];
                ti[mt * 2 + h]  = g_tgtp[pos];
            }
        #pragma unroll
        for (int nt = 0; nt < 4; nt++)
            #pragma unroll
            for (int pp = 0; pp < 2; pp++) {
                int pos = min(jBase + nWarp + nt * 8 + 2 * (lane & 3) + pp, n - 1);
                sqj[nt * 2 + pp] = g_sq[g_perm[pos]];
                tj[nt * 2 + pp]  = g_tgtp[pos];
            }

        unsigned rmax[8], rmin[8], cmax[8], cmin[8];
        #pragma unroll
        for (int q = 0; q < 8; q++) { rmax[q] = 0u; rmin[q] = UINF; cmax[q] = 0u; cmin[q] = UINF; }

        #pragma unroll
        for (int mt = 0; mt < 4; mt++)
            #pragma unroll
            for (int nt = 0; nt < 4; nt++)
                #pragma unroll
                for (int e = 0; e < 4; e++) {
                    int h = e >> 1, pp = e & 1;
                    int ri = mt * 2 + h, cj = nt * 2 + pp;
                    float d2 = fmaxf(sqi[ri] + sqj[cj] - 2.f * acc[mt][nt][(h << 1) | pp], 1e-12f);
                    unsigned b = __float_as_uint(d2);
                    bool same = (ti[ri] == tj[cj]);
                    bool zn   = !same && (ti[ri] == 0 || tj[cj] == 0);
                    if (same) { rmax[ri] = max(rmax[ri], b); cmax[cj] = max(cmax[cj], b); }
                    if (zn)   { rmin[ri] = min(rmin[ri], b); cmin[cj] = min(cmin[cj], b); }
                }

        unsigned* sredmax = (unsigned*)(smem + SM_RED);
        unsigned* sredmin = sredmax + 256;
        sredmax[tid] = 0u;
        sredmin[tid] = UINF;
        __syncthreads();

        #pragma unroll
        for (int mt = 0; mt < 4; mt++)
            #pragma unroll
            for (int h = 0; h < 2; h++) {
                int q = mt * 2 + h;
                int loc = mWarp + mt * 16 + (lane >> 2) + h * 8;
                if (rmax[q]) atomicMax(&sredmax[loc], rmax[q]);
                if (rmin[q] != UINF) atomicMin(&sredmin[loc], rmin[q]);
            }
        #pragma unroll
        for (int nt = 0; nt < 4; nt++)
            #pragma unroll
            for (int pp = 0; pp < 2; pp++) {
                int q = nt * 2 + pp;
                int loc = 128 + nWarp + nt * 8 + 2 * (lane & 3) + pp;
                if (cmax[q]) atomicMax(&sredmax[loc], cmax[q]);
                if (cmin[q] != UINF) atomicMin(&sredmin[loc], cmin[q]);
            }
        __syncthreads();

        {
            int pos = (tid < 128) ? min(iBase + tid, n - 1) : min(jBase + (tid - 128), n - 1);
            if (sredmax[tid]) atomicMax(&g_max2[pos], sredmax[tid]);
            if (sredmin[tid] != UINF) atomicMin(&g_min2[pos], sredmin[tid]);
        }
        __syncthreads();
    }

    // --- last-CTA tail: full loss reduction ----------------------------------
    __threadfence();
    __shared__ int amlast;
    if (tid == 0) amlast = (atomicAdd(&g_done, 1) == (int)gridDim.x - 1);
    __syncthreads();
    if (amlast) {
        int flag = g_flag;
        float s = 0.f;
        for (int i = tid; i < n; i += 256) {
            float ap = sqrtf(__uint_as_float(__ldcg(&g_max2[i])));
            float an = flag ? sqrtf(__uint_as_float(__ldcg(&g_min2[i]))) : 0.f;
            s += fmaxf(ap - an + MARGIN, 0.f);
        }
        float* ssum = (float*)(smem + SM_RED);
        ssum[tid] = s;
        __syncthreads();
        #pragma unroll
        for (int o = 128; o; o >>= 1) {
            if (tid < o) ssum[tid] += ssum[tid + o];
            __syncthreads();
        }
        if (tid == 0) out[0] = ssum[0] / (float)n;
    }
}

// ======================= legacy fp32 fallback (proven, R2) ==================
__global__ void legacy_prep(const float* __restrict__ x, const int* __restrict__ tgt,
                            int n, int d) {
    int warp = (blockIdx.x * blockDim.x + threadIdx.x) >> 5;
    int lane = threadIdx.x & 31;
    if (warp < n) {
        const float4* row = (const float4*)(x + (size_t)warp * d);
        int nv = d >> 2;
        float s = 0.f;
        for (int v = lane; v < nv; v += 32) {
            float4 f = row[v];
            s += f.x * f.x + f.y * f.y + f.z * f.z + f.w * f.w;
        }
        #pragma unroll
        for (int o = 16; o; o >>= 1) s += __shfl_xor_sync(0xffffffffu, s, o);
        if (lane == 0) {
            g_sq[warp]   = s;
            g_max2[warp] = 0u;
            g_min2[warp] = 0x7f800000u;
        }
    }
    if (blockIdx.x == 0) {
        int t0 = tgt[0];
        int loc = 0;
        for (int j = threadIdx.x; j < n; j += blockDim.x) {
            int tj = tgt[j];
            if ((t0 != tj) && (t0 == 0 || tj == 0)) loc = 1;
        }
        int f = __syncthreads_or(loc);
        if (threadIdx.x == 0) g_flag = f;
    }
}

#define LT    128
#define LKT   16
#define LPAD  4
__global__ void __launch_bounds__(256, 2)
gemm_reduce_legacy(const float* __restrict__ x, const int* __restrict__ tgt,
                   int n, int d, int nb) {
    int p = blockIdx.x, bi = 0, rem = p;
    while (rem >= nb - bi) { rem -= (nb - bi); bi++; }
    int bj = bi + rem;
    const int iBase = bi * LT;
    const int jBase = bj * LT;
    const int tid = threadIdx.x;
    const int tx = tid & 15;
    const int ty = tid >> 4;

    __shared__ float As[LKT][LT + LPAD];
    __shared__ float Bs[LKT][LT + LPAD];
    __shared__ unsigned sredmax[2 * LT];
    __shared__ unsigned sredmin[2 * LT];

    float acc[8][8];
    #pragma unroll
    for (int r = 0; r < 8; r++)
        #pragma unroll
        for (int c = 0; c < 8; c++) acc[r][c] = 0.f;

    const int nkt = d / LKT;
    float4 pa[2], pb[2];
    #pragma unroll
    for (int u = 0; u < 2; u++) {
        int idx = tid + u * 256, r = idx >> 2, c4 = idx & 3;
        pa[u] = *(const float4*)(x + (size_t)(iBase + r) * d + c4 * 4);
        pb[u] = *(const float4*)(x + (size_t)(jBase + r) * d + c4 * 4);
    }
    #pragma unroll
    for (int u = 0; u < 2; u++) {
        int idx = tid + u * 256, r = idx >> 2, c4 = idx & 3;
        As[c4*4+0][r]=pa[u].x; As[c4*4+1][r]=pa[u].y; As[c4*4+2][r]=pa[u].z; As[c4*4+3][r]=pa[u].w;
        Bs[c4*4+0][r]=pb[u].x; Bs[c4*4+1][r]=pb[u].y; Bs[c4*4+2][r]=pb[u].z; Bs[c4*4+3][r]=pb[u].w;
    }
    __syncthreads();
    for (int kt = 0; kt < nkt; kt++) {
        if (kt + 1 < nkt) {
            int k0 = (kt + 1) * LKT;
            #pragma unroll
            for (int u = 0; u < 2; u++) {
                int idx = tid + u * 256, r = idx >> 2, c4 = idx & 3;
                pa[u] = *(const float4*)(x + (size_t)(iBase + r) * d + k0 + c4 * 4);
                pb[u] = *(const float4*)(x + (size_t)(jBase + r) * d + k0 + c4 * 4);
            }
        }
        #pragma unroll
        for (int k = 0; k < LKT; k++) {
            float a[8], b[8];
            *(float4*)(a)   = *(const float4*)&As[k][ty*8];
            *(float4*)(a+4) = *(const float4*)&As[k][ty*8+4];
            *(float4*)(b)   = *(const float4*)&Bs[k][tx*8];
            *(float4*)(b+4) = *(const float4*)&Bs[k][tx*8+4];
            #pragma unroll
            for (int r = 0; r < 8; r++)
                #pragma unroll
                for (int c = 0; c < 8; c++) acc[r][c] += a[r] * b[c];
        }
        __syncthreads();
        if (kt + 1 < nkt) {
            #pragma unroll
            for (int u = 0; u < 2; u++) {
                int idx = tid + u * 256, r = idx >> 2, c4 = idx & 3;
                As[c4*4+0][r]=pa[u].x; As[c4*4+1][r]=pa[u].y; As[c4*4+2][r]=pa[u].z; As[c4*4+3][r]=pa[u].w;
                Bs[c4*4+0][r]=pb[u].x; Bs[c4*4+1][r]=pb[u].y; Bs[c4*4+2][r]=pb[u].z; Bs[c4*4+3][r]=pb[u].w;
            }
            __syncthreads();
        }
    }

    float sqi[8], sqj[8];
    int ti8[8], tj8[8];
    #pragma unroll
    for (int r = 0; r < 8; r++) { int i = iBase + ty*8 + r; sqi[r] = g_sq[i]; ti8[r] = tgt[i]; }
    #pragma unroll
    for (int c = 0; c < 8; c++) { int j = jBase + tx*8 + c; sqj[c] = g_sq[j]; tj8[c] = tgt[j]; }

    const float INF = __uint_as_float(0x7f800000u);
    float rmax[8], rmin[8], cmax[8], cmin[8];
    #pragma unroll
    for (int r = 0; r < 8; r++) { rmax[r] = 0.f; rmin[r] = INF; }
    #pragma unroll
    for (int c = 0; c < 8; c++) { cmax[c] = 0.f; cmin[c] = INF; }
    #pragma unroll
    for (int r = 0; r < 8; r++)
        #pragma unroll
        for (int c = 0; c < 8; c++) {
            float d2 = fmaxf(sqi[r] + sqj[c] - 2.f * acc[r][c], 1e-12f);
            bool same = (ti8[r] == tj8[c]);
            bool zn = !same && (ti8[r] == 0 || tj8[c] == 0);
            if (same) { rmax[r] = fmaxf(rmax[r], d2); cmax[c] = fmaxf(cmax[c], d2); }
            if (zn)   { rmin[r] = fminf(rmin[r], d2); cmin[c] = fminf(cmin[c], d2); }
        }
    sredmax[tid] = 0u; sredmin[tid] = 0x7f800000u;
    __syncthreads();
    #pragma unroll
    for (int r = 0; r < 8; r++) {
        atomicMax(&sredmax[ty*8+r], __float_as_uint(rmax[r]));
        atomicMin(&sredmin[ty*8+r], __float_as_uint(rmin[r]));
    }
    #pragma unroll
    for (int c = 0; c < 8; c++) {
        atomicMax(&sredmax[LT + tx*8+c], __float_as_uint(cmax[c]));
        atomicMin(&sredmin[LT + tx*8+c], __float_as_uint(cmin[c]));
    }
    __syncthreads();
    int row = (tid < LT) ? (iBase + tid) : (jBase + (tid - LT));
    atomicMax(&g_max2[row], sredmax[tid]);
    atomicMin(&g_min2[row], sredmin[tid]);
}

__global__ void partial_kernel(int n) {
    __shared__ float ssum[256];
    int flag = g_flag;
    int chunk = (n + NPART - 1) / NPART;
    int beg = blockIdx.x * chunk;
    int end = min(beg + chunk, n);
    float s = 0.f;
    for (int i = beg + (int)threadIdx.x; i < end; i += blockDim.x) {
        float ap = sqrtf(__uint_as_float(g_max2[i]));
        float an = flag ? sqrtf(__uint_as_float(g_min2[i])) : 0.f;
        s += fmaxf(ap - an + MARGIN, 0.f);
    }
    ssum[threadIdx.x] = s;
    __syncthreads();
    #pragma unroll
    for (int o = 128; o; o >>= 1) {
        if (threadIdx.x < o) ssum[threadIdx.x] += ssum[threadIdx.x + o];
        __syncthreads();
    }
    if (threadIdx.x == 0) g_partial[blockIdx.x] = ssum[0];
}

__global__ void final_kernel(float* __restrict__ out, int n) {
    if (threadIdx.x == 0) {
        float s = 0.f;
        #pragma unroll
        for (int b = 0; b < NPART; b++) s += g_partial[b];
        out[0] = s / (float)n;
    }
}

// ======================= host launcher ======================================
extern "C" void kernel_launch(void* const* d_in, const int* in_sizes, int n_in,
                              void* d_out, int out_size) {
    const float* x   = (const float*)d_in[0];
    const int*   tgt = (const int*)d_in[1];   // int32 (JAX x64 disabled)
    int n = in_sizes[1];
    int d = in_sizes[0] / n;

    bool tc_ok = (n % 128 == 0) && (d % BKE == 0) && (d / BKE >= 2) &&
                 (n <= N_MAX) && ((size_t)n * d <= (size_t)N_MAX * D_MAX);
    if (tc_ok) {
        static bool attr_set = false;
        if (!attr_set) {
            cudaFuncSetAttribute(gemm_mma_kernel,
                                 cudaFuncAttributeMaxDynamicSharedMemorySize, SM_TOTAL);
            attr_set = true;
        }
        prep_kernel<<<1 + n / 8, 256>>>(x, tgt, n, d);
        gemm_mma_kernel<<<GRIDSZ, 256, SM_TOTAL>>>((float*)d_out, n, d);
    } else {
        legacy_prep<<<(n + 7) / 8, 256>>>(x, tgt, n, d);
        int nb = n / LT;
        int nblocks = nb * (nb + 1) / 2;
        gemm_reduce_legacy<<<nblocks, 256>>>(x, tgt, n, d, nb);
        partial_kernel<<<NPART, 256>>>(n);
        final_kernel<<<1, 32>>>((float*)d_out, n);
    }
}